// round 14
// baseline (speedup 1.0000x reference)
#include <cuda_runtime.h>
#include <cuda_bf16.h>
#include <math.h>
#include <stdint.h>

typedef unsigned long long ull;

// ---------------------------------------------------------------------------
// Problem dims
// ---------------------------------------------------------------------------
#define B_  16
#define T_  1024
#define D_  8704
#define R_  256
#define H_  72
#define TH3 (3 * H_)   // 216
#define TAU 12
#define BT_ (B_ * T_)

// GEMM1 tiling / unit schedule
#define G1_BK   16
#define KQ_     8                       // k-split factor
#define UCHUNK  (D_ / G1_BK / KQ_)      // 68 chunks per unit
#define NUNITS  (128 * KQ_)             // 1024
#define HELP_LIMIT (NUNITS - 64)        // GRU helpers stop here (tail guard)
#define NTILES  128
#define GRID_MEGA 148                   // 16 GRU + 132 producer CTAs
#define G1_STAGE_FLOATS (G1_BK * 128 + G1_BK * 256)   // 6144
#define G1_STAGE_BYTES  (G1_STAGE_FLOATS * 4)         // 24576
#define G1_DYN  (2 * G1_STAGE_BYTES)                  // 49152

// ---------------------------------------------------------------------------
// Scratch
// ---------------------------------------------------------------------------
__device__ float g_part[KQ_][BT_ * R_];     // split-K partials
__device__ float g_xp[BT_ * TH3];           // [B*T, 3H]
__device__ float g_hseq[BT_ * H_];          // [B*T, H]
__device__ float g_q [BT_];                 // [B, T]
__device__ unsigned int g_unit_ctr;
__device__ unsigned int g_cnt [NTILES];
__device__ unsigned int g_flag[NTILES];

// ---------------------------------------------------------------------------
// helpers
// ---------------------------------------------------------------------------
__device__ __forceinline__ uint32_t smem_u32(const void* p) {
    uint32_t a;
    asm("{ .reg .u64 t; cvta.to.shared.u64 t, %1; cvt.u32.u64 %0, t; }"
        : "=r"(a) : "l"(p));
    return a;
}
__device__ __forceinline__ ull ffma2(ull a, ull b, ull c) {
    ull d; asm("fma.rn.f32x2 %0, %1, %2, %3;" : "=l"(d) : "l"(a), "l"(b), "l"(c));
    return d;
}
__device__ __forceinline__ ull fadd2(ull a, ull b) {
    ull d; asm("add.rn.f32x2 %0, %1, %2;" : "=l"(d) : "l"(a), "l"(b));
    return d;
}
__device__ __forceinline__ ull dupf(float f) {
    ull d; asm("mov.b64 %0, {%1, %1};" : "=l"(d) : "r"(__float_as_uint(f)));
    return d;
}
__device__ __forceinline__ ull packf(float lo, float hi) {
    ull d; asm("mov.b64 %0, {%1, %2};" : "=l"(d)
        : "r"(__float_as_uint(lo)), "r"(__float_as_uint(hi)));
    return d;
}
__device__ __forceinline__ float f2lo(ull u) { return __uint_as_float((uint32_t)u); }
__device__ __forceinline__ float f2hi(ull u) { return __uint_as_float((uint32_t)(u >> 32)); }
__device__ __forceinline__ float tanh_fast(float x) {
    float y; asm("tanh.approx.f32 %0, %1;" : "=f"(y) : "f"(x));
    return y;
}

// ---------------------------------------------------------------------------
// init: zero counters/flags (every graph replay)
// ---------------------------------------------------------------------------
__global__ void init_kernel() {
    const int t = threadIdx.x;
    if (t == 0) g_unit_ctr = 0u;
    if (t < NTILES) { g_cnt[t] = 0u; g_flag[t] = 0u; }
}

// ---------------------------------------------------------------------------
// tile finish: xr_tile = sum8(part) + b_dr (regs) -> GEMM2 -> xp, set flag.
// Arithmetic order identical to R12/R13 (bitwise-equal output).
// ---------------------------------------------------------------------------
__device__ void tile_finish(int tile, int m0,
                            const float* __restrict__ b_dr,
                            const float* __restrict__ w_ih,
                            const float* __restrict__ b_ih) {
    extern __shared__ float dsm[];
    const int tid = threadIdx.x;
    const int tc  = tid & 31;
    const int tr  = tid >> 5;
    const int ar  = tid >> 1, ah = tid & 1;
    const uint32_t sbase = smem_u32(dsm);
    float* As = dsm;
    float* Bs = dsm + G1_BK * 128;

    const bool bval = tid < TH3;
    const float* bptr = w_ih + (size_t)(bval ? tid : 0) * R_;
    const size_t Q = (size_t)BT_ * R_;
    const float* part0 = &g_part[0][0];

    ull acc[8][8];
    #pragma unroll
    for (int p = 0; p < 8; p++)
        #pragma unroll
        for (int j = 0; j < 8; j++) acc[p][j] = 0ull;

    for (int c = 0; c < R_ / G1_BK; c++) {
        __syncthreads();
        {
            const size_t base = (size_t)(m0 + ar) * R_ + c * G1_BK + ah * 8;
            float4 s0 = __ldcg((const float4*)(part0 + base));
            float4 s1 = __ldcg((const float4*)(part0 + base + 4));
            #pragma unroll
            for (int q = 1; q < KQ_; q++) {
                float4 v0 = __ldcg((const float4*)(part0 + q * Q + base));
                float4 v1 = __ldcg((const float4*)(part0 + q * Q + base + 4));
                s0.x += v0.x; s0.y += v0.y; s0.z += v0.z; s0.w += v0.w;
                s1.x += v1.x; s1.y += v1.y; s1.z += v1.z; s1.w += v1.w;
            }
            const float4 bd0 = __ldg((const float4*)(b_dr + c * G1_BK + ah * 8));
            const float4 bd1 = __ldg((const float4*)(b_dr + c * G1_BK + ah * 8 + 4));
            s0.x += bd0.x; s0.y += bd0.y; s0.z += bd0.z; s0.w += bd0.w;
            s1.x += bd1.x; s1.y += bd1.y; s1.z += bd1.z; s1.w += bd1.w;
            const int rb = ah * 8;
            As[(rb + 0) * 128 + ar] = s0.x; As[(rb + 1) * 128 + ar] = s0.y;
            As[(rb + 2) * 128 + ar] = s0.z; As[(rb + 3) * 128 + ar] = s0.w;
            As[(rb + 4) * 128 + ar] = s1.x; As[(rb + 5) * 128 + ar] = s1.y;
            As[(rb + 6) * 128 + ar] = s1.z; As[(rb + 7) * 128 + ar] = s1.w;
        }
        if (bval) {
            const float* bp = bptr + c * G1_BK;
            const float4 b0 = *(const float4*)(bp + 0);
            const float4 b1 = *(const float4*)(bp + 4);
            const float4 b2 = *(const float4*)(bp + 8);
            const float4 b3 = *(const float4*)(bp + 12);
            const float bv[16] = {b0.x, b0.y, b0.z, b0.w, b1.x, b1.y, b1.z, b1.w,
                                  b2.x, b2.y, b2.z, b2.w, b3.x, b3.y, b3.z, b3.w};
            #pragma unroll
            for (int i = 0; i < 16; i++) Bs[i * 256 + tid] = bv[i];
        }
        __syncthreads();
        {
            const uint32_t sA = sbase + tr * 64;
            const float* BsP = Bs + tc * 8;
            #pragma unroll 4
            for (int k = 0; k < G1_BK; k++) {
                ull a[8];
                const uint32_t ab = sA + k * 512;
                asm("ld.shared.v2.b64 {%0,%1}, [%2];" : "=l"(a[0]), "=l"(a[1]) : "r"(ab));
                asm("ld.shared.v2.b64 {%0,%1}, [%2];" : "=l"(a[2]), "=l"(a[3]) : "r"(ab + 16));
                asm("ld.shared.v2.b64 {%0,%1}, [%2];" : "=l"(a[4]), "=l"(a[5]) : "r"(ab + 32));
                asm("ld.shared.v2.b64 {%0,%1}, [%2];" : "=l"(a[6]), "=l"(a[7]) : "r"(ab + 48));
                const float4 b0 = *(const float4*)(BsP + k * 256);
                const float4 b1 = *(const float4*)(BsP + k * 256 + 4);
                ull bd[8];
                bd[0] = dupf(b0.x); bd[1] = dupf(b0.y);
                bd[2] = dupf(b0.z); bd[3] = dupf(b0.w);
                bd[4] = dupf(b1.x); bd[5] = dupf(b1.y);
                bd[6] = dupf(b1.z); bd[7] = dupf(b1.w);
                #pragma unroll
                for (int p = 0; p < 8; p++)
                    #pragma unroll
                    for (int j = 0; j < 8; j++)
                        acc[p][j] = ffma2(a[p], bd[j], acc[p][j]);
            }
        }
    }

    if (tc < 27) {
        const int n0 = tc * 8;
        const float4 bia0 = __ldg((const float4*)(b_ih + n0));
        const float4 bia1 = __ldg((const float4*)(b_ih + n0 + 4));
        #pragma unroll
        for (int p = 0; p < 8; p++) {
            const int r0 = m0 + tr * 16 + 2 * p;
            float4 lo0 = make_float4(f2lo(acc[p][0]) + bia0.x, f2lo(acc[p][1]) + bia0.y,
                                     f2lo(acc[p][2]) + bia0.z, f2lo(acc[p][3]) + bia0.w);
            float4 lo1 = make_float4(f2lo(acc[p][4]) + bia1.x, f2lo(acc[p][5]) + bia1.y,
                                     f2lo(acc[p][6]) + bia1.z, f2lo(acc[p][7]) + bia1.w);
            float4 hi0 = make_float4(f2hi(acc[p][0]) + bia0.x, f2hi(acc[p][1]) + bia0.y,
                                     f2hi(acc[p][2]) + bia0.z, f2hi(acc[p][3]) + bia0.w);
            float4 hi1 = make_float4(f2hi(acc[p][4]) + bia1.x, f2hi(acc[p][5]) + bia1.y,
                                     f2hi(acc[p][6]) + bia1.z, f2hi(acc[p][7]) + bia1.w);
            *(float4*)(g_xp + (size_t)r0 * TH3 + n0)           = lo0;
            *(float4*)(g_xp + (size_t)r0 * TH3 + n0 + 4)       = lo1;
            *(float4*)(g_xp + (size_t)(r0 + 1) * TH3 + n0)     = hi0;
            *(float4*)(g_xp + (size_t)(r0 + 1) * TH3 + n0 + 4) = hi1;
        }
    }
    __threadfence();
    __syncthreads();
    if (tid == 0) atomicExch(&g_flag[tile], 1u);
}

// ---------------------------------------------------------------------------
// try_unit: grab one unit off the global counter (soft limit for helpers)
// and process it (partial GEMM1 + count + possible tile finish).
// Returns false if no unit taken. __noinline__ isolates register pressure
// from the GRU steady-state loop.
// ---------------------------------------------------------------------------
__device__ __noinline__ bool try_unit(unsigned int limit,
                                      const float* __restrict__ A,
                                      const float* __restrict__ Bw,
                                      const float* __restrict__ b_dr,
                                      const float* __restrict__ w_ih,
                                      const float* __restrict__ b_ih) {
    extern __shared__ float dsm[];
    __shared__ unsigned int s_u;
    const int tid = threadIdx.x;

    if (tid == 0) {
        unsigned int cur = atomicAdd(&g_unit_ctr, 0u);
        s_u = (cur >= limit) ? 0xFFFFFFFFu : atomicAdd(&g_unit_ctr, 1u);
    }
    __syncthreads();
    const unsigned int u = s_u;
    __syncthreads();
    if (u >= NUNITS) return false;

    const int tc  = tid & 31;
    const int tr  = tid >> 5;
    const int ar  = tid >> 1, ah = tid & 1;
    const uint32_t sbase = smem_u32(dsm);

    const int jw   = u >> 7;       // wave (tile-within-batch)
    const int rr   = u & 127;
    const int bb   = rr >> 3;      // batch
    const int kq   = rr & 7;       // k-slice
    const int tile = bb * 8 + jw;
    const int m0   = tile * 128;
    const size_t koff = (size_t)kq * (UCHUNK * G1_BK);

    {
        ull acc[8][8];
        #pragma unroll
        for (int p = 0; p < 8; p++)
            #pragma unroll
            for (int j = 0; j < 8; j++) acc[p][j] = 0ull;

        const float* aptr = A + (size_t)(m0 + ar) * D_ + koff + ah * 8;
        const float* bptr = Bw + (size_t)tid * D_ + koff;

        float4 areg[2], breg[4];
        areg[0] = *(const float4*)(aptr + 0);
        areg[1] = *(const float4*)(aptr + 4);
        breg[0] = *(const float4*)(bptr + 0);
        breg[1] = *(const float4*)(bptr + 4);
        breg[2] = *(const float4*)(bptr + 8);
        breg[3] = *(const float4*)(bptr + 12);
        {
            float* As = dsm;
            float* Bs = dsm + G1_BK * 128;
            const float av[8] = {areg[0].x, areg[0].y, areg[0].z, areg[0].w,
                                 areg[1].x, areg[1].y, areg[1].z, areg[1].w};
            #pragma unroll
            for (int i = 0; i < 8; i++) As[(ah * 8 + i) * 128 + ar] = av[i];
            const float bv[16] = {breg[0].x, breg[0].y, breg[0].z, breg[0].w,
                                  breg[1].x, breg[1].y, breg[1].z, breg[1].w,
                                  breg[2].x, breg[2].y, breg[2].z, breg[2].w,
                                  breg[3].x, breg[3].y, breg[3].z, breg[3].w};
            #pragma unroll
            for (int i = 0; i < 16; i++) Bs[i * 256 + tid] = bv[i];
        }
        __syncthreads();

        for (int c = 0; c < UCHUNK; c++) {
            const int s = c & 1;
            if (c + 1 < UCHUNK) {
                const float* ap = aptr + (size_t)(c + 1) * G1_BK;
                const float* bp = bptr + (size_t)(c + 1) * G1_BK;
                areg[0] = *(const float4*)(ap + 0);
                areg[1] = *(const float4*)(ap + 4);
                breg[0] = *(const float4*)(bp + 0);
                breg[1] = *(const float4*)(bp + 4);
                breg[2] = *(const float4*)(bp + 8);
                breg[3] = *(const float4*)(bp + 12);
            }
            {
                const uint32_t sA = sbase + s * G1_STAGE_BYTES + tr * 64;
                const float*  Bs = dsm + s * G1_STAGE_FLOATS + G1_BK * 128 + tc * 8;
                #pragma unroll 4
                for (int k = 0; k < G1_BK; k++) {
                    ull a[8];
                    const uint32_t ab = sA + k * 512;
                    asm("ld.shared.v2.b64 {%0,%1}, [%2];" : "=l"(a[0]), "=l"(a[1]) : "r"(ab));
                    asm("ld.shared.v2.b64 {%0,%1}, [%2];" : "=l"(a[2]), "=l"(a[3]) : "r"(ab + 16));
                    asm("ld.shared.v2.b64 {%0,%1}, [%2];" : "=l"(a[4]), "=l"(a[5]) : "r"(ab + 32));
                    asm("ld.shared.v2.b64 {%0,%1}, [%2];" : "=l"(a[6]), "=l"(a[7]) : "r"(ab + 48));
                    const float4 b0 = *(const float4*)(Bs + k * 256);
                    const float4 b1 = *(const float4*)(Bs + k * 256 + 4);
                    ull bd[8];
                    bd[0] = dupf(b0.x); bd[1] = dupf(b0.y);
                    bd[2] = dupf(b0.z); bd[3] = dupf(b0.w);
                    bd[4] = dupf(b1.x); bd[5] = dupf(b1.y);
                    bd[6] = dupf(b1.z); bd[7] = dupf(b1.w);
                    #pragma unroll
                    for (int p = 0; p < 8; p++)
                        #pragma unroll
                        for (int j = 0; j < 8; j++)
                            acc[p][j] = ffma2(a[p], bd[j], acc[p][j]);
                }
            }
            if (c + 1 < UCHUNK) {
                float* As = dsm + (s ^ 1) * G1_STAGE_FLOATS;
                float* Bs = As + G1_BK * 128;
                const float av[8] = {areg[0].x, areg[0].y, areg[0].z, areg[0].w,
                                     areg[1].x, areg[1].y, areg[1].z, areg[1].w};
                #pragma unroll
                for (int i = 0; i < 8; i++) As[(ah * 8 + i) * 128 + ar] = av[i];
                const float bv[16] = {breg[0].x, breg[0].y, breg[0].z, breg[0].w,
                                      breg[1].x, breg[1].y, breg[1].z, breg[1].w,
                                      breg[2].x, breg[2].y, breg[2].z, breg[2].w,
                                      breg[3].x, breg[3].y, breg[3].z, breg[3].w};
                #pragma unroll
                for (int i = 0; i < 16; i++) Bs[i * 256 + tid] = bv[i];
            }
            __syncthreads();
        }

        float* Cp = &g_part[kq][0];
        const int n0 = tc * 8;
        #pragma unroll
        for (int p = 0; p < 8; p++) {
            const int r0 = m0 + tr * 16 + 2 * p;
            float4 lo0 = make_float4(f2lo(acc[p][0]), f2lo(acc[p][1]),
                                     f2lo(acc[p][2]), f2lo(acc[p][3]));
            float4 lo1 = make_float4(f2lo(acc[p][4]), f2lo(acc[p][5]),
                                     f2lo(acc[p][6]), f2lo(acc[p][7]));
            float4 hi0 = make_float4(f2hi(acc[p][0]), f2hi(acc[p][1]),
                                     f2hi(acc[p][2]), f2hi(acc[p][3]));
            float4 hi1 = make_float4(f2hi(acc[p][4]), f2hi(acc[p][5]),
                                     f2hi(acc[p][6]), f2hi(acc[p][7]));
            *(float4*)(Cp + (size_t)r0 * R_ + n0)           = lo0;
            *(float4*)(Cp + (size_t)r0 * R_ + n0 + 4)       = lo1;
            *(float4*)(Cp + (size_t)(r0 + 1) * R_ + n0)     = hi0;
            *(float4*)(Cp + (size_t)(r0 + 1) * R_ + n0 + 4) = hi1;
        }
    }

    // count; 8th unit runs the tile finish
    __threadfence();
    __syncthreads();
    if (tid == 0) s_u = atomicAdd(&g_cnt[tile], 1u);
    __syncthreads();
    const unsigned int old = s_u;
    __syncthreads();
    if (old == 7u) {
        __threadfence();
        tile_finish(tile, m0, b_dr, w_ih, b_ih);
    }
    return true;
}

// ---------------------------------------------------------------------------
// GRU wait-with-help: poll the flag; while unset, steal producer units
// (soft-limited so the tail stays clean).
// ---------------------------------------------------------------------------
__device__ void wait_flag_help(unsigned int* f,
                               const float* A, const float* Bw,
                               const float* b_dr, const float* w_ih,
                               const float* b_ih) {
    __shared__ unsigned int s_d;
    for (;;) {
        if (threadIdx.x == 0) s_d = atomicAdd(f, 0u);
        __syncthreads();
        const unsigned int d = s_d;
        __syncthreads();
        if (d != 0u) break;
        if (!try_unit(HELP_LIMIT, A, Bw, b_dr, w_ih, b_ih)) {
            if (threadIdx.x == 0) __nanosleep(300);
            __syncthreads();
        }
    }
    if (threadIdx.x == 0) __threadfence();
    __syncthreads();
}

// ---------------------------------------------------------------------------
// GRU branch: R13 structure, with work-stealing waits
// ---------------------------------------------------------------------------
__device__ void gru_branch(int b,
                           const float* __restrict__ w_hh,
                           const float* __restrict__ b_hh,
                           const float* A, const float* Bw,
                           const float* b_dr, const float* w_ih,
                           const float* b_ih) {
    __shared__ __align__(16) float h[H_];
    __shared__ float hp[TH3];
    __shared__ float xv[TH3];

    const int j = threadIdx.x;

    ull w2[36];
    ull bh2 = 0ull;
    if (j < TH3) {
        #pragma unroll
        for (int i = 0; i < 36; i++)
            w2[i] = packf(w_hh[j * H_ + 2 * i], w_hh[j * H_ + 2 * i + 1]);
        bh2 = packf(b_hh[j], 0.f);
    }
    if (j < H_) h[j] = 0.f;
    __syncthreads();

    const uint32_t hb = smem_u32(h);
    const float* xprow = g_xp + (size_t)b * T_ * TH3;
    float* hrow = g_hseq + (size_t)b * T_ * H_;

    wait_flag_help(&g_flag[b * 8], A, Bw, b_dr, w_ih, b_ih);
    float xpv0 = (j < TH3) ? __ldcg(xprow + j) : 0.f;
    float xpv1 = (j < TH3) ? __ldcg(xprow + TH3 + j) : 0.f;
    __syncthreads();

    for (int t = 0; t < T_; t++) {
        if (((t + 2) & 127) == 0 && (t + 2) < T_)
            wait_flag_help(&g_flag[b * 8 + ((t + 2) >> 7)],
                           A, Bw, b_dr, w_ih, b_ih);

        if (j < TH3) {
            ull a0 = bh2, a1 = 0ull, a2 = 0ull, a3 = 0ull;
            #pragma unroll
            for (int i = 0; i < 18; i++) {
                ull p0, p1;
                asm volatile("ld.shared.v2.b64 {%0,%1}, [%2];"
                             : "=l"(p0), "=l"(p1) : "r"(hb + i * 16));
                if (i & 1) {
                    a2 = ffma2(w2[2 * i],     p0, a2);
                    a3 = ffma2(w2[2 * i + 1], p1, a3);
                } else {
                    a0 = ffma2(w2[2 * i],     p0, a0);
                    a1 = ffma2(w2[2 * i + 1], p1, a1);
                }
            }
            ull s = fadd2(fadd2(a0, a2), fadd2(a1, a3));
            hp[j] = f2lo(s) + f2hi(s);
            xv[j] = xpv0;
        }
        float xnext = 0.f;
        if (j < TH3 && t + 2 < T_) xnext = __ldcg(xprow + (size_t)(t + 2) * TH3 + j);
        __syncthreads();

        if (j < H_) {
            float r  = __fdividef(1.f, 1.f + __expf(-(xv[j]        + hp[j])));
            float z  = __fdividef(1.f, 1.f + __expf(-(xv[j + H_]   + hp[j + H_])));
            float n  = tanh_fast(xv[j + 2 * H_] + r * hp[j + 2 * H_]);
            float hn = (1.f - z) * n + z * h[j];
            h[j] = hn;
            hrow[(size_t)t * H_ + j] = hn;
        }
        __syncthreads();

        xpv0 = xpv1;
        xpv1 = xnext;
    }
}

// ---------------------------------------------------------------------------
// mega kernel: CTAs 0-15 = GRU consumers (with stealing), 16-147 = producers
// ---------------------------------------------------------------------------
__global__ __launch_bounds__(256, 1)
void mega_kernel(const float* __restrict__ x,
                 const float* __restrict__ w_dr,
                 const float* __restrict__ b_dr,
                 const float* __restrict__ w_ih,
                 const float* __restrict__ b_ih,
                 const float* __restrict__ w_hh,
                 const float* __restrict__ b_hh) {
    if (blockIdx.x < 16) {
        gru_branch(blockIdx.x, w_hh, b_hh, x, w_dr, b_dr, w_ih, b_ih);
    } else {
        while (try_unit(NUNITS, x, w_dr, b_dr, w_ih, b_ih)) {}
    }
}

// ---------------------------------------------------------------------------
// q[b,t] = dot(hseq[b,t,:], w_reg) + b_reg
// ---------------------------------------------------------------------------
__global__ __launch_bounds__(128)
void qgemv_kernel(const float* __restrict__ hseq,
                  const float* __restrict__ w_reg,
                  const float* __restrict__ b_reg,
                  float* __restrict__ q)
{
    __shared__ float sh[128 * 73];
    __shared__ float swr[H_];

    const int tid  = threadIdx.x;
    const int row0 = blockIdx.x * 128;

    const float4* src = (const float4*)(hseq + (size_t)row0 * H_);
    for (int i = tid; i < 128 * (H_ / 4); i += 128) {
        const int r  = i / (H_ / 4);
        const int c4 = i - r * (H_ / 4);
        float4 v = src[i];
        float* d = &sh[r * 73 + c4 * 4];
        d[0] = v.x; d[1] = v.y; d[2] = v.z; d[3] = v.w;
    }
    if (tid < H_) swr[tid] = w_reg[tid];
    __syncthreads();

    float acc = b_reg[0];
    const float* hr = &sh[tid * 73];
    #pragma unroll
    for (int i = 0; i < H_; i++) acc = fmaf(hr[i], swr[i], acc);
    q[row0 + tid] = acc;
}

// ---------------------------------------------------------------------------
// sitp + sigmoid heads
// ---------------------------------------------------------------------------
__global__ __launch_bounds__(1024, 1)
void sitp_kernel(const float* __restrict__ q,
                 const int*   __restrict__ xlen,
                 const float* __restrict__ nlm_w1, const float* __restrict__ nlm_b1,
                 const float* __restrict__ nlm_w2, const float* __restrict__ nlm_b2,
                 const float* __restrict__ lm_w,   const float* __restrict__ lm_b,
                 float* __restrict__ out)
{
    const int b = blockIdx.x;
    const int t = threadIdx.x;

    __shared__ float qs[T_];
    __shared__ float ws[T_];
    __shared__ float wqs[T_];
    __shared__ float warpsum[32];

    const int len = xlen[b];
    const float qv = q[b * T_ + t];
    const bool valid = t < len;

    qs[t] = qv;
    const float wv = valid ? expf(-qv) : 0.f;
    ws[t]  = wv;
    wqs[t] = wv * qv;
    __syncthreads();

    float c = 0.f;
    if (valid) {
        float xmin = qv;
        #pragma unroll
        for (int d = 1; d < TAU; d++) {
            int s = t - d;
            if (s >= 0) xmin = fminf(xmin, qs[s]);
        }
        float num = 0.f, den = 0.f;
        #pragma unroll
        for (int d = 0; d < TAU; d++) {
            int s = t + d;
            if (s < T_) { num += wqs[s]; den += ws[s]; }
        }
        float y = (den > 0.f) ? num / fmaxf(den, 1e-30f) : 0.f;
        c = 0.5f * y + 0.5f * xmin;
    }

    #pragma unroll
    for (int off = 16; off > 0; off >>= 1)
        c += __shfl_down_sync(0xFFFFFFFFu, c, off);
    const int wid  = t >> 5;
    const int lane = t & 31;
    if (lane == 0) warpsum[wid] = c;
    __syncthreads();
    if (wid == 0) {
        float v = warpsum[lane];
        #pragma unroll
        for (int off = 16; off > 0; off >>= 1)
            v += __shfl_down_sync(0xFFFFFFFFu, v, off);
        if (lane == 0) {
            const float s        = v / (float)len;
            const float relative = 1.f / (1.f + expf(-s));
            const float mapped   = (1.f / (1.f + expf(-(nlm_w1[0] * relative + nlm_b1[0]))))
                                   * nlm_w2[0] + nlm_b2[0];
            const float aligned  = lm_w[0] * mapped + lm_b[0];
            out[b]          = relative;
            out[B_ + b]     = mapped;
            out[2 * B_ + b] = aligned;
        }
    }
}

// ---------------------------------------------------------------------------
// Launch
// ---------------------------------------------------------------------------
extern "C" void kernel_launch(void* const* d_in, const int* in_sizes, int n_in,
                              void* d_out, int out_size)
{
    const float* x     = (const float*)d_in[0];
    const int*   x_len = (const int*)  d_in[1];
    const float* w_dr  = (const float*)d_in[2];
    const float* b_dr  = (const float*)d_in[3];
    const float* w_ih  = (const float*)d_in[4];
    const float* w_hh  = (const float*)d_in[5];
    const float* b_ih  = (const float*)d_in[6];
    const float* b_hh  = (const float*)d_in[7];
    const float* w_reg = (const float*)d_in[8];
    const float* b_reg = (const float*)d_in[9];
    const float* nlm_w1 = (const float*)d_in[10];
    const float* nlm_b1 = (const float*)d_in[11];
    const float* nlm_w2 = (const float*)d_in[12];
    const float* nlm_b2 = (const float*)d_in[13];
    const float* lm_w   = (const float*)d_in[14];
    const float* lm_b   = (const float*)d_in[15];
    float* out = (float*)d_out;

    float* hs;   cudaGetSymbolAddress((void**)&hs,   g_hseq);
    float* qq;   cudaGetSymbolAddress((void**)&qq,   g_q);

    static bool attr_done = false;
    if (!attr_done) {
        cudaFuncSetAttribute(mega_kernel,
                             cudaFuncAttributeMaxDynamicSharedMemorySize, G1_DYN);
        attr_done = true;
    }

    // reset flags/counters (graph replays)
    init_kernel<<<1, 128>>>();
    // fused producer/consumer with GRU work-stealing
    mega_kernel<<<GRID_MEGA, 256, G1_DYN>>>(x, w_dr, b_dr, w_ih, b_ih, w_hh, b_hh);
    // q = hseq @ w_reg + b_reg
    qgemv_kernel<<<BT_ / 128, 128>>>(hs, w_reg, b_reg, qq);
    // sitp windows + heads
    sitp_kernel<<<B_, T_>>>(qq, x_len, nlm_w1, nlm_b1, nlm_w2, nlm_b2,
                            lm_w, lm_b, out);
}

// round 15
// speedup vs baseline: 1.0524x; 1.0524x over previous
#include <cuda_runtime.h>
#include <cuda_bf16.h>
#include <math.h>
#include <stdint.h>

typedef unsigned long long ull;

// ---------------------------------------------------------------------------
// Problem dims
// ---------------------------------------------------------------------------
#define B_  16
#define T_  1024
#define D_  8704
#define R_  256
#define H_  72
#define TH3 (3 * H_)   // 216
#define TAU 12
#define BT_ (B_ * T_)

// GEMM1 tiling / unit schedule
#define G1_BK   16
#define KQ_     8                       // k-split factor
#define UCHUNK  (D_ / G1_BK / KQ_)      // 68 chunks per unit
#define NUNITS  (128 * KQ_)             // 1024
#define NTILES  128
#define GRID_MEGA 148                   // 16 GRU + 132 producer CTAs
#define NTHREADS 512
#define G1_STAGE_FLOATS (G1_BK * 128 + G1_BK * 256)   // 6144
#define G1_STAGE_BYTES  (G1_STAGE_FLOATS * 4)         // 24576
#define G1_DYN  (2 * G1_STAGE_BYTES)                  // 49152

// ---------------------------------------------------------------------------
// Scratch
// ---------------------------------------------------------------------------
__device__ float g_part[KQ_][BT_ * R_];     // split-K partials
__device__ float g_xp[BT_ * TH3];           // [B*T, 3H]
__device__ float g_hseq[BT_ * H_];          // [B*T, H]
__device__ float g_q [BT_];                 // [B, T]
__device__ unsigned int g_unit_ctr;
__device__ unsigned int g_cnt [NTILES];
__device__ unsigned int g_flag[NTILES];

// ---------------------------------------------------------------------------
// helpers
// ---------------------------------------------------------------------------
__device__ __forceinline__ uint32_t smem_u32(const void* p) {
    uint32_t a;
    asm("{ .reg .u64 t; cvta.to.shared.u64 t, %1; cvt.u32.u64 %0, t; }"
        : "=r"(a) : "l"(p));
    return a;
}
__device__ __forceinline__ ull ffma2(ull a, ull b, ull c) {
    ull d; asm("fma.rn.f32x2 %0, %1, %2, %3;" : "=l"(d) : "l"(a), "l"(b), "l"(c));
    return d;
}
__device__ __forceinline__ ull fadd2(ull a, ull b) {
    ull d; asm("add.rn.f32x2 %0, %1, %2;" : "=l"(d) : "l"(a), "l"(b));
    return d;
}
__device__ __forceinline__ ull dupf(float f) {
    ull d; asm("mov.b64 %0, {%1, %1};" : "=l"(d) : "r"(__float_as_uint(f)));
    return d;
}
__device__ __forceinline__ ull packf(float lo, float hi) {
    ull d; asm("mov.b64 %0, {%1, %2};" : "=l"(d)
        : "r"(__float_as_uint(lo)), "r"(__float_as_uint(hi)));
    return d;
}
__device__ __forceinline__ float f2lo(ull u) { return __uint_as_float((uint32_t)u); }
__device__ __forceinline__ float f2hi(ull u) { return __uint_as_float((uint32_t)(u >> 32)); }
__device__ __forceinline__ float tanh_fast(float x) {
    float y; asm("tanh.approx.f32 %0, %1;" : "=f"(y) : "f"(x));
    return y;
}

// block-wide wait on a release flag
__device__ __forceinline__ void wait_flag(unsigned int* f) {
    if (threadIdx.x == 0) {
        while (atomicAdd(f, 0u) == 0u) { __nanosleep(200); }
        __threadfence();
    }
    __syncthreads();
}

// ---------------------------------------------------------------------------
// init: zero counters/flags (every graph replay)
// ---------------------------------------------------------------------------
__global__ void init_kernel() {
    const int t = threadIdx.x;
    if (t == 0) g_unit_ctr = 0u;
    if (t < NTILES) { g_cnt[t] = 0u; g_flag[t] = 0u; }
}

// ---------------------------------------------------------------------------
// tile finish (512 threads): xr_tile = sum8(part) + b_dr (regs) -> GEMM2
// -> xp, set flag. Same per-element arithmetic order as R13 (bitwise equal).
// ---------------------------------------------------------------------------
__device__ void tile_finish(int tile, int m0,
                            const float* __restrict__ b_dr,
                            const float* __restrict__ w_ih,
                            const float* __restrict__ b_ih) {
    extern __shared__ float dsm[];
    const int tid = threadIdx.x;
    const int tc  = tid & 31;          // col group: cols tc*8..+8
    const int tr  = (tid >> 5) & 15;   // row group: rows tr*8..+8
    const int ar  = tid >> 2, ah = tid & 3;    // A staging: row, k-quarter
    const int br  = tid >> 1, bh = tid & 1;    // B staging: row, k-half
    const uint32_t sbase = smem_u32(dsm);
    float* As = dsm;
    float* Bs = dsm + G1_BK * 128;

    const bool bval = br < TH3;
    const float* bptr = w_ih + (size_t)(bval ? br : 0) * R_;
    const size_t Q = (size_t)BT_ * R_;
    const float* part0 = &g_part[0][0];

    ull acc[4][8];
    #pragma unroll
    for (int p = 0; p < 4; p++)
        #pragma unroll
        for (int j = 0; j < 8; j++) acc[p][j] = 0ull;

    for (int c = 0; c < R_ / G1_BK; c++) {
        __syncthreads();
        // stage A: each thread sums one float4 over 8 slabs + bias
        {
            const size_t base = (size_t)(m0 + ar) * R_ + c * G1_BK + ah * 4;
            float4 s0 = __ldcg((const float4*)(part0 + base));
            #pragma unroll
            for (int q = 1; q < KQ_; q++) {
                float4 v0 = __ldcg((const float4*)(part0 + q * Q + base));
                s0.x += v0.x; s0.y += v0.y; s0.z += v0.z; s0.w += v0.w;
            }
            const float4 bd0 = __ldg((const float4*)(b_dr + c * G1_BK + ah * 4));
            s0.x += bd0.x; s0.y += bd0.y; s0.z += bd0.z; s0.w += bd0.w;
            const int kb = ah * 4;
            As[(kb + 0) * 128 + ar] = s0.x; As[(kb + 1) * 128 + ar] = s0.y;
            As[(kb + 2) * 128 + ar] = s0.z; As[(kb + 3) * 128 + ar] = s0.w;
        }
        // stage B: 8 k-values of w_ih row br
        if (bval) {
            const float* bp = bptr + c * G1_BK + bh * 8;
            const float4 b0 = *(const float4*)(bp + 0);
            const float4 b1 = *(const float4*)(bp + 4);
            const float bv[8] = {b0.x, b0.y, b0.z, b0.w, b1.x, b1.y, b1.z, b1.w};
            const int kb = bh * 8;
            #pragma unroll
            for (int i = 0; i < 8; i++) Bs[(kb + i) * 256 + br] = bv[i];
        }
        __syncthreads();
        // compute chunk
        {
            const uint32_t sA = sbase + tr * 32;
            const float* BsP = Bs + tc * 8;
            #pragma unroll 4
            for (int k = 0; k < G1_BK; k++) {
                ull a[4];
                const uint32_t ab = sA + k * 512;
                asm("ld.shared.v2.b64 {%0,%1}, [%2];" : "=l"(a[0]), "=l"(a[1]) : "r"(ab));
                asm("ld.shared.v2.b64 {%0,%1}, [%2];" : "=l"(a[2]), "=l"(a[3]) : "r"(ab + 16));
                const float4 b0 = *(const float4*)(BsP + k * 256);
                const float4 b1 = *(const float4*)(BsP + k * 256 + 4);
                ull bd[8];
                bd[0] = dupf(b0.x); bd[1] = dupf(b0.y);
                bd[2] = dupf(b0.z); bd[3] = dupf(b0.w);
                bd[4] = dupf(b1.x); bd[5] = dupf(b1.y);
                bd[6] = dupf(b1.z); bd[7] = dupf(b1.w);
                #pragma unroll
                for (int p = 0; p < 4; p++)
                    #pragma unroll
                    for (int j = 0; j < 8; j++)
                        acc[p][j] = ffma2(a[p], bd[j], acc[p][j]);
            }
        }
    }

    if (tc < 27) {
        const int n0 = tc * 8;
        const float4 bia0 = __ldg((const float4*)(b_ih + n0));
        const float4 bia1 = __ldg((const float4*)(b_ih + n0 + 4));
        #pragma unroll
        for (int p = 0; p < 4; p++) {
            const int r0 = m0 + tr * 8 + 2 * p;
            float4 lo0 = make_float4(f2lo(acc[p][0]) + bia0.x, f2lo(acc[p][1]) + bia0.y,
                                     f2lo(acc[p][2]) + bia0.z, f2lo(acc[p][3]) + bia0.w);
            float4 lo1 = make_float4(f2lo(acc[p][4]) + bia1.x, f2lo(acc[p][5]) + bia1.y,
                                     f2lo(acc[p][6]) + bia1.z, f2lo(acc[p][7]) + bia1.w);
            float4 hi0 = make_float4(f2hi(acc[p][0]) + bia0.x, f2hi(acc[p][1]) + bia0.y,
                                     f2hi(acc[p][2]) + bia0.z, f2hi(acc[p][3]) + bia0.w);
            float4 hi1 = make_float4(f2hi(acc[p][4]) + bia1.x, f2hi(acc[p][5]) + bia1.y,
                                     f2hi(acc[p][6]) + bia1.z, f2hi(acc[p][7]) + bia1.w);
            *(float4*)(g_xp + (size_t)r0 * TH3 + n0)           = lo0;
            *(float4*)(g_xp + (size_t)r0 * TH3 + n0 + 4)       = lo1;
            *(float4*)(g_xp + (size_t)(r0 + 1) * TH3 + n0)     = hi0;
            *(float4*)(g_xp + (size_t)(r0 + 1) * TH3 + n0 + 4) = hi1;
        }
    }
    __threadfence();
    __syncthreads();
    if (tid == 0) atomicExch(&g_flag[tile], 1u);
}

// ---------------------------------------------------------------------------
// producer branch (512 threads): dynamic units; per-thread 8x8 tile.
// ---------------------------------------------------------------------------
__device__ void producer_branch(const float* __restrict__ A,
                                const float* __restrict__ Bw,
                                const float* __restrict__ b_dr,
                                const float* __restrict__ w_ih,
                                const float* __restrict__ b_ih) {
    extern __shared__ float dsm[];
    __shared__ unsigned int s_bcast;
    const int tid = threadIdx.x;
    const int tc  = tid & 31;          // col group
    const int tr  = (tid >> 5) & 15;   // row group (8 rows)
    const int ar  = tid >> 2, ah = tid & 3;    // A ldg: row, k-quarter (4 floats)
    const int br  = tid >> 1, bh = tid & 1;    // B ldg: row, k-half (8 floats)
    const uint32_t sbase = smem_u32(dsm);

    for (;;) {
        if (tid == 0) s_bcast = atomicAdd(&g_unit_ctr, 1u);
        __syncthreads();
        const unsigned int u = s_bcast;
        __syncthreads();
        if (u >= NUNITS) break;

        const int jw   = u >> 7;       // wave (tile-within-batch)
        const int rr   = u & 127;
        const int bb   = rr >> 3;      // batch
        const int kq   = rr & 7;       // k-slice
        const int tile = bb * 8 + jw;
        const int m0   = tile * 128;
        const size_t koff = (size_t)kq * (UCHUNK * G1_BK);

        ull acc[4][8];
        #pragma unroll
        for (int p = 0; p < 4; p++)
            #pragma unroll
            for (int j = 0; j < 8; j++) acc[p][j] = 0ull;

        const float* aptr = A + (size_t)(m0 + ar) * D_ + koff + ah * 4;
        const float* bptr = Bw + (size_t)br * D_ + koff + bh * 8;

        float4 areg, breg0, breg1;

        // prologue: chunk 0 -> stage 0
        areg  = *(const float4*)(aptr);
        breg0 = *(const float4*)(bptr);
        breg1 = *(const float4*)(bptr + 4);
        {
            float* As = dsm;
            float* Bs = dsm + G1_BK * 128;
            const int ka = ah * 4;
            As[(ka + 0) * 128 + ar] = areg.x; As[(ka + 1) * 128 + ar] = areg.y;
            As[(ka + 2) * 128 + ar] = areg.z; As[(ka + 3) * 128 + ar] = areg.w;
            const float bv[8] = {breg0.x, breg0.y, breg0.z, breg0.w,
                                 breg1.x, breg1.y, breg1.z, breg1.w};
            const int kb = bh * 8;
            #pragma unroll
            for (int i = 0; i < 8; i++) Bs[(kb + i) * 256 + br] = bv[i];
        }
        __syncthreads();

        for (int c = 0; c < UCHUNK; c++) {
            const int s = c & 1;
            if (c + 1 < UCHUNK) {
                areg  = *(const float4*)(aptr + (size_t)(c + 1) * G1_BK);
                breg0 = *(const float4*)(bptr + (size_t)(c + 1) * G1_BK);
                breg1 = *(const float4*)(bptr + (size_t)(c + 1) * G1_BK + 4);
            }
            {
                const uint32_t sA = sbase + s * G1_STAGE_BYTES + tr * 32;
                const float*  Bs = dsm + s * G1_STAGE_FLOATS + G1_BK * 128 + tc * 8;
                #pragma unroll 4
                for (int k = 0; k < G1_BK; k++) {
                    ull a[4];
                    const uint32_t ab = sA + k * 512;
                    asm("ld.shared.v2.b64 {%0,%1}, [%2];" : "=l"(a[0]), "=l"(a[1]) : "r"(ab));
                    asm("ld.shared.v2.b64 {%0,%1}, [%2];" : "=l"(a[2]), "=l"(a[3]) : "r"(ab + 16));
                    const float4 b0 = *(const float4*)(Bs + k * 256);
                    const float4 b1 = *(const float4*)(Bs + k * 256 + 4);
                    ull bd[8];
                    bd[0] = dupf(b0.x); bd[1] = dupf(b0.y);
                    bd[2] = dupf(b0.z); bd[3] = dupf(b0.w);
                    bd[4] = dupf(b1.x); bd[5] = dupf(b1.y);
                    bd[6] = dupf(b1.z); bd[7] = dupf(b1.w);
                    #pragma unroll
                    for (int p = 0; p < 4; p++)
                        #pragma unroll
                        for (int j = 0; j < 8; j++)
                            acc[p][j] = ffma2(a[p], bd[j], acc[p][j]);
                }
            }
            if (c + 1 < UCHUNK) {
                float* As = dsm + (s ^ 1) * G1_STAGE_FLOATS;
                float* Bs = As + G1_BK * 128;
                const int ka = ah * 4;
                As[(ka + 0) * 128 + ar] = areg.x; As[(ka + 1) * 128 + ar] = areg.y;
                As[(ka + 2) * 128 + ar] = areg.z; As[(ka + 3) * 128 + ar] = areg.w;
                const float bv[8] = {breg0.x, breg0.y, breg0.z, breg0.w,
                                     breg1.x, breg1.y, breg1.z, breg1.w};
                const int kb = bh * 8;
                #pragma unroll
                for (int i = 0; i < 8; i++) Bs[(kb + i) * 256 + br] = bv[i];
            }
            __syncthreads();
        }

        // epilogue: write partial tile
        {
            float* Cp = &g_part[kq][0];
            const int n0 = tc * 8;
            #pragma unroll
            for (int p = 0; p < 4; p++) {
                const int r0 = m0 + tr * 8 + 2 * p;
                float4 lo0 = make_float4(f2lo(acc[p][0]), f2lo(acc[p][1]),
                                         f2lo(acc[p][2]), f2lo(acc[p][3]));
                float4 lo1 = make_float4(f2lo(acc[p][4]), f2lo(acc[p][5]),
                                         f2lo(acc[p][6]), f2lo(acc[p][7]));
                float4 hi0 = make_float4(f2hi(acc[p][0]), f2hi(acc[p][1]),
                                         f2hi(acc[p][2]), f2hi(acc[p][3]));
                float4 hi1 = make_float4(f2hi(acc[p][4]), f2hi(acc[p][5]),
                                         f2hi(acc[p][6]), f2hi(acc[p][7]));
                *(float4*)(Cp + (size_t)r0 * R_ + n0)           = lo0;
                *(float4*)(Cp + (size_t)r0 * R_ + n0 + 4)       = lo1;
                *(float4*)(Cp + (size_t)(r0 + 1) * R_ + n0)     = hi0;
                *(float4*)(Cp + (size_t)(r0 + 1) * R_ + n0 + 4) = hi1;
            }
        }

        // count; 8th unit runs the tile finish
        __threadfence();
        __syncthreads();
        if (tid == 0) s_bcast = atomicAdd(&g_cnt[tile], 1u);
        __syncthreads();
        const unsigned int old = s_bcast;
        __syncthreads();
        if (old == 7u) {
            __threadfence();
            tile_finish(tile, m0, b_dr, w_ih, b_ih);
        }
    }
}

// ---------------------------------------------------------------------------
// GRU branch (threads >= TH3 idle through barriers)
// ---------------------------------------------------------------------------
__device__ void gru_branch(int b,
                           const float* __restrict__ w_hh,
                           const float* __restrict__ b_hh) {
    __shared__ __align__(16) float h[H_];
    __shared__ float hp[TH3];
    __shared__ float xv[TH3];

    const int j = threadIdx.x;

    ull w2[36];
    ull bh2 = 0ull;
    if (j < TH3) {
        #pragma unroll
        for (int i = 0; i < 36; i++)
            w2[i] = packf(w_hh[j * H_ + 2 * i], w_hh[j * H_ + 2 * i + 1]);
        bh2 = packf(b_hh[j], 0.f);
    }
    if (j < H_) h[j] = 0.f;

    const uint32_t hb = smem_u32(h);
    const float* xprow = g_xp + (size_t)b * T_ * TH3;
    float* hrow = g_hseq + (size_t)b * T_ * H_;

    wait_flag(&g_flag[b * 8]);          // tile 0 ready (also syncs h init)
    float xpv0 = (j < TH3) ? __ldcg(xprow + j) : 0.f;
    float xpv1 = (j < TH3) ? __ldcg(xprow + TH3 + j) : 0.f;
    __syncthreads();

    for (int t = 0; t < T_; t++) {
        if (((t + 2) & 127) == 0 && (t + 2) < T_)
            wait_flag(&g_flag[b * 8 + ((t + 2) >> 7)]);

        if (j < TH3) {
            ull a0 = bh2, a1 = 0ull, a2 = 0ull, a3 = 0ull;
            #pragma unroll
            for (int i = 0; i < 18; i++) {
                ull p0, p1;
                asm volatile("ld.shared.v2.b64 {%0,%1}, [%2];"
                             : "=l"(p0), "=l"(p1) : "r"(hb + i * 16));
                if (i & 1) {
                    a2 = ffma2(w2[2 * i],     p0, a2);
                    a3 = ffma2(w2[2 * i + 1], p1, a3);
                } else {
                    a0 = ffma2(w2[2 * i],     p0, a0);
                    a1 = ffma2(w2[2 * i + 1], p1, a1);
                }
            }
            ull s = fadd2(fadd2(a0, a2), fadd2(a1, a3));
            hp[j] = f2lo(s) + f2hi(s);
            xv[j] = xpv0;
        }
        float xnext = 0.f;
        if (j < TH3 && t + 2 < T_) xnext = __ldcg(xprow + (size_t)(t + 2) * TH3 + j);
        __syncthreads();

        if (j < H_) {
            float r  = __fdividef(1.f, 1.f + __expf(-(xv[j]        + hp[j])));
            float z  = __fdividef(1.f, 1.f + __expf(-(xv[j + H_]   + hp[j + H_])));
            float n  = tanh_fast(xv[j + 2 * H_] + r * hp[j + 2 * H_]);
            float hn = (1.f - z) * n + z * h[j];
            h[j] = hn;
            hrow[(size_t)t * H_ + j] = hn;
        }
        __syncthreads();

        xpv0 = xpv1;
        xpv1 = xnext;
    }
}

// ---------------------------------------------------------------------------
// mega kernel: CTAs 0-15 = GRU consumers, 16-147 = producers
// ---------------------------------------------------------------------------
__global__ __launch_bounds__(NTHREADS, 1)
void mega_kernel(const float* __restrict__ x,
                 const float* __restrict__ w_dr,
                 const float* __restrict__ b_dr,
                 const float* __restrict__ w_ih,
                 const float* __restrict__ b_ih,
                 const float* __restrict__ w_hh,
                 const float* __restrict__ b_hh) {
    if (blockIdx.x < 16) gru_branch(blockIdx.x, w_hh, b_hh);
    else                 producer_branch(x, w_dr, b_dr, w_ih, b_ih);
}

// ---------------------------------------------------------------------------
// q[b,t] = dot(hseq[b,t,:], w_reg) + b_reg
// ---------------------------------------------------------------------------
__global__ __launch_bounds__(128)
void qgemv_kernel(const float* __restrict__ hseq,
                  const float* __restrict__ w_reg,
                  const float* __restrict__ b_reg,
                  float* __restrict__ q)
{
    __shared__ float sh[128 * 73];
    __shared__ float swr[H_];

    const int tid  = threadIdx.x;
    const int row0 = blockIdx.x * 128;

    const float4* src = (const float4*)(hseq + (size_t)row0 * H_);
    for (int i = tid; i < 128 * (H_ / 4); i += 128) {
        const int r  = i / (H_ / 4);
        const int c4 = i - r * (H_ / 4);
        float4 v = src[i];
        float* d = &sh[r * 73 + c4 * 4];
        d[0] = v.x; d[1] = v.y; d[2] = v.z; d[3] = v.w;
    }
    if (tid < H_) swr[tid] = w_reg[tid];
    __syncthreads();

    float acc = b_reg[0];
    const float* hr = &sh[tid * 73];
    #pragma unroll
    for (int i = 0; i < H_; i++) acc = fmaf(hr[i], swr[i], acc);
    q[row0 + tid] = acc;
}

// ---------------------------------------------------------------------------
// sitp + sigmoid heads
// ---------------------------------------------------------------------------
__global__ __launch_bounds__(1024, 1)
void sitp_kernel(const float* __restrict__ q,
                 const int*   __restrict__ xlen,
                 const float* __restrict__ nlm_w1, const float* __restrict__ nlm_b1,
                 const float* __restrict__ nlm_w2, const float* __restrict__ nlm_b2,
                 const float* __restrict__ lm_w,   const float* __restrict__ lm_b,
                 float* __restrict__ out)
{
    const int b = blockIdx.x;
    const int t = threadIdx.x;

    __shared__ float qs[T_];
    __shared__ float ws[T_];
    __shared__ float wqs[T_];
    __shared__ float warpsum[32];

    const int len = xlen[b];
    const float qv = q[b * T_ + t];
    const bool valid = t < len;

    qs[t] = qv;
    const float wv = valid ? expf(-qv) : 0.f;
    ws[t]  = wv;
    wqs[t] = wv * qv;
    __syncthreads();

    float c = 0.f;
    if (valid) {
        float xmin = qv;
        #pragma unroll
        for (int d = 1; d < TAU; d++) {
            int s = t - d;
            if (s >= 0) xmin = fminf(xmin, qs[s]);
        }
        float num = 0.f, den = 0.f;
        #pragma unroll
        for (int d = 0; d < TAU; d++) {
            int s = t + d;
            if (s < T_) { num += wqs[s]; den += ws[s]; }
        }
        float y = (den > 0.f) ? num / fmaxf(den, 1e-30f) : 0.f;
        c = 0.5f * y + 0.5f * xmin;
    }

    #pragma unroll
    for (int off = 16; off > 0; off >>= 1)
        c += __shfl_down_sync(0xFFFFFFFFu, c, off);
    const int wid  = t >> 5;
    const int lane = t & 31;
    if (lane == 0) warpsum[wid] = c;
    __syncthreads();
    if (wid == 0) {
        float v = warpsum[lane];
        #pragma unroll
        for (int off = 16; off > 0; off >>= 1)
            v += __shfl_down_sync(0xFFFFFFFFu, v, off);
        if (lane == 0) {
            const float s        = v / (float)len;
            const float relative = 1.f / (1.f + expf(-s));
            const float mapped   = (1.f / (1.f + expf(-(nlm_w1[0] * relative + nlm_b1[0]))))
                                   * nlm_w2[0] + nlm_b2[0];
            const float aligned  = lm_w[0] * mapped + lm_b[0];
            out[b]          = relative;
            out[B_ + b]     = mapped;
            out[2 * B_ + b] = aligned;
        }
    }
}

// ---------------------------------------------------------------------------
// Launch
// ---------------------------------------------------------------------------
extern "C" void kernel_launch(void* const* d_in, const int* in_sizes, int n_in,
                              void* d_out, int out_size)
{
    const float* x     = (const float*)d_in[0];
    const int*   x_len = (const int*)  d_in[1];
    const float* w_dr  = (const float*)d_in[2];
    const float* b_dr  = (const float*)d_in[3];
    const float* w_ih  = (const float*)d_in[4];
    const float* w_hh  = (const float*)d_in[5];
    const float* b_ih  = (const float*)d_in[6];
    const float* b_hh  = (const float*)d_in[7];
    const float* w_reg = (const float*)d_in[8];
    const float* b_reg = (const float*)d_in[9];
    const float* nlm_w1 = (const float*)d_in[10];
    const float* nlm_b1 = (const float*)d_in[11];
    const float* nlm_w2 = (const float*)d_in[12];
    const float* nlm_b2 = (const float*)d_in[13];
    const float* lm_w   = (const float*)d_in[14];
    const float* lm_b   = (const float*)d_in[15];
    float* out = (float*)d_out;

    float* hs;   cudaGetSymbolAddress((void**)&hs,   g_hseq);
    float* qq;   cudaGetSymbolAddress((void**)&qq,   g_q);

    static bool attr_done = false;
    if (!attr_done) {
        cudaFuncSetAttribute(mega_kernel,
                             cudaFuncAttributeMaxDynamicSharedMemorySize, G1_DYN);
        attr_done = true;
    }

    // reset flags/counters (graph replays)
    init_kernel<<<1, 128>>>();
    // fused producer/consumer (512-thread CTAs, 4 warps/SMSP)
    mega_kernel<<<GRID_MEGA, NTHREADS, G1_DYN>>>(x, w_dr, b_dr, w_ih, b_ih,
                                                 w_hh, b_hh);
    // q = hseq @ w_reg + b_reg
    qgemv_kernel<<<BT_ / 128, 128>>>(hs, w_reg, b_reg, qq);
    // sitp windows + heads
    sitp_kernel<<<B_, T_>>>(qq, x_len, nlm_w1, nlm_b1, nlm_w2, nlm_b2,
                            lm_w, lm_b, out);
}

// round 16
// speedup vs baseline: 1.1421x; 1.0852x over previous
#include <cuda_runtime.h>
#include <cuda_bf16.h>
#include <math.h>
#include <stdint.h>

typedef unsigned long long ull;

// ---------------------------------------------------------------------------
// Problem dims
// ---------------------------------------------------------------------------
#define B_  16
#define T_  1024
#define D_  8704
#define R_  256
#define H_  72
#define TH3 (3 * H_)   // 216
#define TAU 12
#define BT_ (B_ * T_)

// GEMM1 tiling / unit schedule
#define G1_BK   16
#define KQ_     8                       // k-split factor
#define UCHUNK  (D_ / G1_BK / KQ_)      // 68 chunks per unit
#define NUNITS  (128 * KQ_)             // 1024
#define NTILES  128
#define GRID_MEGA 148                   // 16 GRU + 132 producer CTAs
#define G1_STAGE_FLOATS (G1_BK * 128 + G1_BK * 256)   // 6144
#define G1_STAGE_BYTES  (G1_STAGE_FLOATS * 4)         // 24576
#define G1_DYN  (2 * G1_STAGE_BYTES)                  // 49152

// ---------------------------------------------------------------------------
// Scratch
// ---------------------------------------------------------------------------
__device__ float g_part[KQ_][BT_ * R_];     // split-K partials
__device__ float g_xp[BT_ * TH3];           // [B*T, 3H]
__device__ float g_q [BT_];                 // [B, T]
__device__ unsigned int g_unit_ctr;
__device__ unsigned int g_cnt [NTILES];
__device__ unsigned int g_flag[NTILES];

// ---------------------------------------------------------------------------
// helpers
// ---------------------------------------------------------------------------
__device__ __forceinline__ uint32_t smem_u32(const void* p) {
    uint32_t a;
    asm("{ .reg .u64 t; cvta.to.shared.u64 t, %1; cvt.u32.u64 %0, t; }"
        : "=r"(a) : "l"(p));
    return a;
}
__device__ __forceinline__ ull ffma2(ull a, ull b, ull c) {
    ull d; asm("fma.rn.f32x2 %0, %1, %2, %3;" : "=l"(d) : "l"(a), "l"(b), "l"(c));
    return d;
}
__device__ __forceinline__ ull fadd2(ull a, ull b) {
    ull d; asm("add.rn.f32x2 %0, %1, %2;" : "=l"(d) : "l"(a), "l"(b));
    return d;
}
__device__ __forceinline__ ull dupf(float f) {
    ull d; asm("mov.b64 %0, {%1, %1};" : "=l"(d) : "r"(__float_as_uint(f)));
    return d;
}
__device__ __forceinline__ ull packf(float lo, float hi) {
    ull d; asm("mov.b64 %0, {%1, %2};" : "=l"(d)
        : "r"(__float_as_uint(lo)), "r"(__float_as_uint(hi)));
    return d;
}
__device__ __forceinline__ float f2lo(ull u) { return __uint_as_float((uint32_t)u); }
__device__ __forceinline__ float f2hi(ull u) { return __uint_as_float((uint32_t)(u >> 32)); }
__device__ __forceinline__ float tanh_fast(float x) {
    float y; asm("tanh.approx.f32 %0, %1;" : "=f"(y) : "f"(x));
    return y;
}

// block-wide wait on a release flag
__device__ __forceinline__ void wait_flag(unsigned int* f) {
    if (threadIdx.x == 0) {
        while (atomicAdd(f, 0u) == 0u) { __nanosleep(200); }
        __threadfence();
    }
    __syncthreads();
}

// ---------------------------------------------------------------------------
// init: zero counters/flags (every graph replay)
// ---------------------------------------------------------------------------
__global__ void init_kernel() {
    const int t = threadIdx.x;
    if (t == 0) g_unit_ctr = 0u;
    if (t < NTILES) { g_cnt[t] = 0u; g_flag[t] = 0u; }
}

// ---------------------------------------------------------------------------
// tile finish: xr_tile = sum8(part) + b_dr (regs) -> GEMM2 -> xp, set flag.
// Arithmetic order identical to R12/R13 (bitwise-equal output).
// ---------------------------------------------------------------------------
__device__ void tile_finish(int tile, int m0,
                            const float* __restrict__ b_dr,
                            const float* __restrict__ w_ih,
                            const float* __restrict__ b_ih) {
    extern __shared__ float dsm[];
    const int tid = threadIdx.x;
    const int tc  = tid & 31;
    const int tr  = tid >> 5;
    const int ar  = tid >> 1, ah = tid & 1;
    const uint32_t sbase = smem_u32(dsm);
    float* As = dsm;
    float* Bs = dsm + G1_BK * 128;

    const bool bval = tid < TH3;
    const float* bptr = w_ih + (size_t)(bval ? tid : 0) * R_;
    const size_t Q = (size_t)BT_ * R_;
    const float* part0 = &g_part[0][0];

    ull acc[8][8];
    #pragma unroll
    for (int p = 0; p < 8; p++)
        #pragma unroll
        for (int j = 0; j < 8; j++) acc[p][j] = 0ull;

    for (int c = 0; c < R_ / G1_BK; c++) {
        __syncthreads();
        {
            const size_t base = (size_t)(m0 + ar) * R_ + c * G1_BK + ah * 8;
            float4 s0 = __ldcg((const float4*)(part0 + base));
            float4 s1 = __ldcg((const float4*)(part0 + base + 4));
            #pragma unroll
            for (int q = 1; q < KQ_; q++) {
                float4 v0 = __ldcg((const float4*)(part0 + q * Q + base));
                float4 v1 = __ldcg((const float4*)(part0 + q * Q + base + 4));
                s0.x += v0.x; s0.y += v0.y; s0.z += v0.z; s0.w += v0.w;
                s1.x += v1.x; s1.y += v1.y; s1.z += v1.z; s1.w += v1.w;
            }
            const float4 bd0 = __ldg((const float4*)(b_dr + c * G1_BK + ah * 8));
            const float4 bd1 = __ldg((const float4*)(b_dr + c * G1_BK + ah * 8 + 4));
            s0.x += bd0.x; s0.y += bd0.y; s0.z += bd0.z; s0.w += bd0.w;
            s1.x += bd1.x; s1.y += bd1.y; s1.z += bd1.z; s1.w += bd1.w;
            const int rb = ah * 8;
            As[(rb + 0) * 128 + ar] = s0.x; As[(rb + 1) * 128 + ar] = s0.y;
            As[(rb + 2) * 128 + ar] = s0.z; As[(rb + 3) * 128 + ar] = s0.w;
            As[(rb + 4) * 128 + ar] = s1.x; As[(rb + 5) * 128 + ar] = s1.y;
            As[(rb + 6) * 128 + ar] = s1.z; As[(rb + 7) * 128 + ar] = s1.w;
        }
        if (bval) {
            const float* bp = bptr + c * G1_BK;
            const float4 b0 = *(const float4*)(bp + 0);
            const float4 b1 = *(const float4*)(bp + 4);
            const float4 b2 = *(const float4*)(bp + 8);
            const float4 b3 = *(const float4*)(bp + 12);
            const float bv[16] = {b0.x, b0.y, b0.z, b0.w, b1.x, b1.y, b1.z, b1.w,
                                  b2.x, b2.y, b2.z, b2.w, b3.x, b3.y, b3.z, b3.w};
            #pragma unroll
            for (int i = 0; i < 16; i++) Bs[i * 256 + tid] = bv[i];
        }
        __syncthreads();
        {
            const uint32_t sA = sbase + tr * 64;
            const float* BsP = Bs + tc * 8;
            #pragma unroll 4
            for (int k = 0; k < G1_BK; k++) {
                ull a[8];
                const uint32_t ab = sA + k * 512;
                asm("ld.shared.v2.b64 {%0,%1}, [%2];" : "=l"(a[0]), "=l"(a[1]) : "r"(ab));
                asm("ld.shared.v2.b64 {%0,%1}, [%2];" : "=l"(a[2]), "=l"(a[3]) : "r"(ab + 16));
                asm("ld.shared.v2.b64 {%0,%1}, [%2];" : "=l"(a[4]), "=l"(a[5]) : "r"(ab + 32));
                asm("ld.shared.v2.b64 {%0,%1}, [%2];" : "=l"(a[6]), "=l"(a[7]) : "r"(ab + 48));
                const float4 b0 = *(const float4*)(BsP + k * 256);
                const float4 b1 = *(const float4*)(BsP + k * 256 + 4);
                ull bd[8];
                bd[0] = dupf(b0.x); bd[1] = dupf(b0.y);
                bd[2] = dupf(b0.z); bd[3] = dupf(b0.w);
                bd[4] = dupf(b1.x); bd[5] = dupf(b1.y);
                bd[6] = dupf(b1.z); bd[7] = dupf(b1.w);
                #pragma unroll
                for (int p = 0; p < 8; p++)
                    #pragma unroll
                    for (int j = 0; j < 8; j++)
                        acc[p][j] = ffma2(a[p], bd[j], acc[p][j]);
            }
        }
    }

    if (tc < 27) {
        const int n0 = tc * 8;
        const float4 bia0 = __ldg((const float4*)(b_ih + n0));
        const float4 bia1 = __ldg((const float4*)(b_ih + n0 + 4));
        #pragma unroll
        for (int p = 0; p < 8; p++) {
            const int r0 = m0 + tr * 16 + 2 * p;
            float4 lo0 = make_float4(f2lo(acc[p][0]) + bia0.x, f2lo(acc[p][1]) + bia0.y,
                                     f2lo(acc[p][2]) + bia0.z, f2lo(acc[p][3]) + bia0.w);
            float4 lo1 = make_float4(f2lo(acc[p][4]) + bia1.x, f2lo(acc[p][5]) + bia1.y,
                                     f2lo(acc[p][6]) + bia1.z, f2lo(acc[p][7]) + bia1.w);
            float4 hi0 = make_float4(f2hi(acc[p][0]) + bia0.x, f2hi(acc[p][1]) + bia0.y,
                                     f2hi(acc[p][2]) + bia0.z, f2hi(acc[p][3]) + bia0.w);
            float4 hi1 = make_float4(f2hi(acc[p][4]) + bia1.x, f2hi(acc[p][5]) + bia1.y,
                                     f2hi(acc[p][6]) + bia1.z, f2hi(acc[p][7]) + bia1.w);
            *(float4*)(g_xp + (size_t)r0 * TH3 + n0)           = lo0;
            *(float4*)(g_xp + (size_t)r0 * TH3 + n0 + 4)       = lo1;
            *(float4*)(g_xp + (size_t)(r0 + 1) * TH3 + n0)     = hi0;
            *(float4*)(g_xp + (size_t)(r0 + 1) * TH3 + n0 + 4) = hi1;
        }
    }
    __threadfence();
    __syncthreads();
    if (tid == 0) atomicExch(&g_flag[tile], 1u);
}

// ---------------------------------------------------------------------------
// producer branch (256 threads, R13-identical): dynamic units, wave-major.
// ---------------------------------------------------------------------------
__device__ void producer_branch(const float* __restrict__ A,
                                const float* __restrict__ Bw,
                                const float* __restrict__ b_dr,
                                const float* __restrict__ w_ih,
                                const float* __restrict__ b_ih) {
    extern __shared__ float dsm[];
    __shared__ unsigned int s_bcast;
    const int tid = threadIdx.x;
    const int tc  = tid & 31;
    const int tr  = tid >> 5;
    const int ar  = tid >> 1, ah = tid & 1;
    const uint32_t sbase = smem_u32(dsm);

    for (;;) {
        if (tid == 0) s_bcast = atomicAdd(&g_unit_ctr, 1u);
        __syncthreads();
        const unsigned int u = s_bcast;
        __syncthreads();
        if (u >= NUNITS) break;

        const int jw   = u >> 7;
        const int rr   = u & 127;
        const int bb   = rr >> 3;
        const int kq   = rr & 7;
        const int tile = bb * 8 + jw;
        const int m0   = tile * 128;
        const size_t koff = (size_t)kq * (UCHUNK * G1_BK);

        {
            ull acc[8][8];
            #pragma unroll
            for (int p = 0; p < 8; p++)
                #pragma unroll
                for (int j = 0; j < 8; j++) acc[p][j] = 0ull;

            const float* aptr = A + (size_t)(m0 + ar) * D_ + koff + ah * 8;
            const float* bptr = Bw + (size_t)tid * D_ + koff;

            float4 areg[2], breg[4];
            areg[0] = *(const float4*)(aptr + 0);
            areg[1] = *(const float4*)(aptr + 4);
            breg[0] = *(const float4*)(bptr + 0);
            breg[1] = *(const float4*)(bptr + 4);
            breg[2] = *(const float4*)(bptr + 8);
            breg[3] = *(const float4*)(bptr + 12);
            {
                float* As = dsm;
                float* Bs = dsm + G1_BK * 128;
                const float av[8] = {areg[0].x, areg[0].y, areg[0].z, areg[0].w,
                                     areg[1].x, areg[1].y, areg[1].z, areg[1].w};
                #pragma unroll
                for (int i = 0; i < 8; i++) As[(ah * 8 + i) * 128 + ar] = av[i];
                const float bv[16] = {breg[0].x, breg[0].y, breg[0].z, breg[0].w,
                                      breg[1].x, breg[1].y, breg[1].z, breg[1].w,
                                      breg[2].x, breg[2].y, breg[2].z, breg[2].w,
                                      breg[3].x, breg[3].y, breg[3].z, breg[3].w};
                #pragma unroll
                for (int i = 0; i < 16; i++) Bs[i * 256 + tid] = bv[i];
            }
            __syncthreads();

            for (int c = 0; c < UCHUNK; c++) {
                const int s = c & 1;
                if (c + 1 < UCHUNK) {
                    const float* ap = aptr + (size_t)(c + 1) * G1_BK;
                    const float* bp = bptr + (size_t)(c + 1) * G1_BK;
                    areg[0] = *(const float4*)(ap + 0);
                    areg[1] = *(const float4*)(ap + 4);
                    breg[0] = *(const float4*)(bp + 0);
                    breg[1] = *(const float4*)(bp + 4);
                    breg[2] = *(const float4*)(bp + 8);
                    breg[3] = *(const float4*)(bp + 12);
                }
                {
                    const uint32_t sA = sbase + s * G1_STAGE_BYTES + tr * 64;
                    const float*  Bs = dsm + s * G1_STAGE_FLOATS + G1_BK * 128 + tc * 8;
                    #pragma unroll 4
                    for (int k = 0; k < G1_BK; k++) {
                        ull a[8];
                        const uint32_t ab = sA + k * 512;
                        asm("ld.shared.v2.b64 {%0,%1}, [%2];" : "=l"(a[0]), "=l"(a[1]) : "r"(ab));
                        asm("ld.shared.v2.b64 {%0,%1}, [%2];" : "=l"(a[2]), "=l"(a[3]) : "r"(ab + 16));
                        asm("ld.shared.v2.b64 {%0,%1}, [%2];" : "=l"(a[4]), "=l"(a[5]) : "r"(ab + 32));
                        asm("ld.shared.v2.b64 {%0,%1}, [%2];" : "=l"(a[6]), "=l"(a[7]) : "r"(ab + 48));
                        const float4 b0 = *(const float4*)(Bs + k * 256);
                        const float4 b1 = *(const float4*)(Bs + k * 256 + 4);
                        ull bd[8];
                        bd[0] = dupf(b0.x); bd[1] = dupf(b0.y);
                        bd[2] = dupf(b0.z); bd[3] = dupf(b0.w);
                        bd[4] = dupf(b1.x); bd[5] = dupf(b1.y);
                        bd[6] = dupf(b1.z); bd[7] = dupf(b1.w);
                        #pragma unroll
                        for (int p = 0; p < 8; p++)
                            #pragma unroll
                            for (int j = 0; j < 8; j++)
                                acc[p][j] = ffma2(a[p], bd[j], acc[p][j]);
                    }
                }
                if (c + 1 < UCHUNK) {
                    float* As = dsm + (s ^ 1) * G1_STAGE_FLOATS;
                    float* Bs = As + G1_BK * 128;
                    const float av[8] = {areg[0].x, areg[0].y, areg[0].z, areg[0].w,
                                         areg[1].x, areg[1].y, areg[1].z, areg[1].w};
                    #pragma unroll
                    for (int i = 0; i < 8; i++) As[(ah * 8 + i) * 128 + ar] = av[i];
                    const float bv[16] = {breg[0].x, breg[0].y, breg[0].z, breg[0].w,
                                          breg[1].x, breg[1].y, breg[1].z, breg[1].w,
                                          breg[2].x, breg[2].y, breg[2].z, breg[2].w,
                                          breg[3].x, breg[3].y, breg[3].z, breg[3].w};
                    #pragma unroll
                    for (int i = 0; i < 16; i++) Bs[i * 256 + tid] = bv[i];
                }
                __syncthreads();
            }

            float* Cp = &g_part[kq][0];
            const int n0 = tc * 8;
            #pragma unroll
            for (int p = 0; p < 8; p++) {
                const int r0 = m0 + tr * 16 + 2 * p;
                float4 lo0 = make_float4(f2lo(acc[p][0]), f2lo(acc[p][1]),
                                         f2lo(acc[p][2]), f2lo(acc[p][3]));
                float4 lo1 = make_float4(f2lo(acc[p][4]), f2lo(acc[p][5]),
                                         f2lo(acc[p][6]), f2lo(acc[p][7]));
                float4 hi0 = make_float4(f2hi(acc[p][0]), f2hi(acc[p][1]),
                                         f2hi(acc[p][2]), f2hi(acc[p][3]));
                float4 hi1 = make_float4(f2hi(acc[p][4]), f2hi(acc[p][5]),
                                         f2hi(acc[p][6]), f2hi(acc[p][7]));
                *(float4*)(Cp + (size_t)r0 * R_ + n0)           = lo0;
                *(float4*)(Cp + (size_t)r0 * R_ + n0 + 4)       = lo1;
                *(float4*)(Cp + (size_t)(r0 + 1) * R_ + n0)     = hi0;
                *(float4*)(Cp + (size_t)(r0 + 1) * R_ + n0 + 4) = hi1;
            }
        }

        __threadfence();
        __syncthreads();
        if (tid == 0) s_bcast = atomicAdd(&g_cnt[tile], 1u);
        __syncthreads();
        const unsigned int old = s_bcast;
        __syncthreads();
        if (old == 7u) {
            __threadfence();
            tile_finish(tile, m0, b_dr, w_ih, b_ih);
        }
    }
}

// ---------------------------------------------------------------------------
// GRU branch (256 threads): warps 0-6 run the recurrence (R13-identical),
// warp 7 (threads 224-255) computes q[b,t] = dot(h_t, w_reg)+b_reg off the
// critical path (h is stable from post-update sync until next gates phase).
// ---------------------------------------------------------------------------
__device__ void gru_branch(int b,
                           const float* __restrict__ w_hh,
                           const float* __restrict__ b_hh,
                           const float* __restrict__ w_reg,
                           const float* __restrict__ b_reg) {
    __shared__ __align__(16) float h[H_];
    __shared__ float hp[TH3];
    __shared__ float xv[TH3];

    const int j = threadIdx.x;
    const int lane = j & 31;

    ull w2[36];
    ull bh2 = 0ull;
    if (j < TH3) {
        #pragma unroll
        for (int i = 0; i < 36; i++)
            w2[i] = packf(w_hh[j * H_ + 2 * i], w_hh[j * H_ + 2 * i + 1]);
        bh2 = packf(b_hh[j], 0.f);
    }
    // warp 7: q-projection weights
    float wr0 = 0.f, wr1 = 0.f, wr2 = 0.f, brg = 0.f;
    if (j >= 224) {
        wr0 = w_reg[lane];
        wr1 = w_reg[lane + 32];
        wr2 = (lane < 8) ? w_reg[lane + 64] : 0.f;
        brg = b_reg[0];
    }
    if (j < H_) h[j] = 0.f;

    const uint32_t hb = smem_u32(h);
    const float* xprow = g_xp + (size_t)b * T_ * TH3;
    float* qrow = g_q + (size_t)b * T_;

    wait_flag(&g_flag[b * 8]);          // tile 0 ready (also syncs h init)
    float xpv0 = (j < TH3) ? __ldcg(xprow + j) : 0.f;
    float xpv1 = (j < TH3) ? __ldcg(xprow + TH3 + j) : 0.f;
    __syncthreads();

    for (int t = 0; t < T_; t++) {
        if (((t + 2) & 127) == 0 && (t + 2) < T_)
            wait_flag(&g_flag[b * 8 + ((t + 2) >> 7)]);

        if (j < TH3) {
            ull a0 = bh2, a1 = 0ull, a2 = 0ull, a3 = 0ull;
            #pragma unroll
            for (int i = 0; i < 18; i++) {
                ull p0, p1;
                asm volatile("ld.shared.v2.b64 {%0,%1}, [%2];"
                             : "=l"(p0), "=l"(p1) : "r"(hb + i * 16));
                if (i & 1) {
                    a2 = ffma2(w2[2 * i],     p0, a2);
                    a3 = ffma2(w2[2 * i + 1], p1, a3);
                } else {
                    a0 = ffma2(w2[2 * i],     p0, a0);
                    a1 = ffma2(w2[2 * i + 1], p1, a1);
                }
            }
            ull s = fadd2(fadd2(a0, a2), fadd2(a1, a3));
            hp[j] = f2lo(s) + f2hi(s);
            xv[j] = xpv0;
        }
        float xnext = 0.f;
        if (j < TH3 && t + 2 < T_) xnext = __ldcg(xprow + (size_t)(t + 2) * TH3 + j);
        __syncthreads();

        if (j < H_) {
            float r  = __fdividef(1.f, 1.f + __expf(-(xv[j]        + hp[j])));
            float z  = __fdividef(1.f, 1.f + __expf(-(xv[j + H_]   + hp[j + H_])));
            float n  = tanh_fast(xv[j + 2 * H_] + r * hp[j + 2 * H_]);
            float hn = (1.f - z) * n + z * h[j];
            h[j] = hn;
        }
        __syncthreads();

        // warp 7: q for step t (runs during warps 0-6's next matvec phase;
        // h stays stable until the next gates phase behind another barrier)
        if (j >= 224) {
            float p = h[lane] * wr0 + h[lane + 32] * wr1;
            if (lane < 8) p += h[lane + 64] * wr2;
            #pragma unroll
            for (int off = 16; off > 0; off >>= 1)
                p += __shfl_down_sync(0xFFFFFFFFu, p, off);
            if (lane == 0) qrow[t] = p + brg;
        }

        xpv0 = xpv1;
        xpv1 = xnext;
    }
}

// ---------------------------------------------------------------------------
// mega kernel: CTAs 0-15 = GRU consumers (with inline q), 16-147 = producers
// ---------------------------------------------------------------------------
__global__ __launch_bounds__(256, 1)
void mega_kernel(const float* __restrict__ x,
                 const float* __restrict__ w_dr,
                 const float* __restrict__ b_dr,
                 const float* __restrict__ w_ih,
                 const float* __restrict__ b_ih,
                 const float* __restrict__ w_hh,
                 const float* __restrict__ b_hh,
                 const float* __restrict__ w_reg,
                 const float* __restrict__ b_reg) {
    if (blockIdx.x < 16) gru_branch(blockIdx.x, w_hh, b_hh, w_reg, b_reg);
    else                 producer_branch(x, w_dr, b_dr, w_ih, b_ih);
}

// ---------------------------------------------------------------------------
// sitp + sigmoid heads
// ---------------------------------------------------------------------------
__global__ __launch_bounds__(1024, 1)
void sitp_kernel(const float* __restrict__ q,
                 const int*   __restrict__ xlen,
                 const float* __restrict__ nlm_w1, const float* __restrict__ nlm_b1,
                 const float* __restrict__ nlm_w2, const float* __restrict__ nlm_b2,
                 const float* __restrict__ lm_w,   const float* __restrict__ lm_b,
                 float* __restrict__ out)
{
    const int b = blockIdx.x;
    const int t = threadIdx.x;

    __shared__ float qs[T_];
    __shared__ float ws[T_];
    __shared__ float wqs[T_];
    __shared__ float warpsum[32];

    const int len = xlen[b];
    const float qv = q[b * T_ + t];
    const bool valid = t < len;

    qs[t] = qv;
    const float wv = valid ? expf(-qv) : 0.f;
    ws[t]  = wv;
    wqs[t] = wv * qv;
    __syncthreads();

    float c = 0.f;
    if (valid) {
        float xmin = qv;
        #pragma unroll
        for (int d = 1; d < TAU; d++) {
            int s = t - d;
            if (s >= 0) xmin = fminf(xmin, qs[s]);
        }
        float num = 0.f, den = 0.f;
        #pragma unroll
        for (int d = 0; d < TAU; d++) {
            int s = t + d;
            if (s < T_) { num += wqs[s]; den += ws[s]; }
        }
        float y = (den > 0.f) ? num / fmaxf(den, 1e-30f) : 0.f;
        c = 0.5f * y + 0.5f * xmin;
    }

    #pragma unroll
    for (int off = 16; off > 0; off >>= 1)
        c += __shfl_down_sync(0xFFFFFFFFu, c, off);
    const int wid  = t >> 5;
    const int lane = t & 31;
    if (lane == 0) warpsum[wid] = c;
    __syncthreads();
    if (wid == 0) {
        float v = warpsum[lane];
        #pragma unroll
        for (int off = 16; off > 0; off >>= 1)
            v += __shfl_down_sync(0xFFFFFFFFu, v, off);
        if (lane == 0) {
            const float s        = v / (float)len;
            const float relative = 1.f / (1.f + expf(-s));
            const float mapped   = (1.f / (1.f + expf(-(nlm_w1[0] * relative + nlm_b1[0]))))
                                   * nlm_w2[0] + nlm_b2[0];
            const float aligned  = lm_w[0] * mapped + lm_b[0];
            out[b]          = relative;
            out[B_ + b]     = mapped;
            out[2 * B_ + b] = aligned;
        }
    }
}

// ---------------------------------------------------------------------------
// Launch
// ---------------------------------------------------------------------------
extern "C" void kernel_launch(void* const* d_in, const int* in_sizes, int n_in,
                              void* d_out, int out_size)
{
    const float* x     = (const float*)d_in[0];
    const int*   x_len = (const int*)  d_in[1];
    const float* w_dr  = (const float*)d_in[2];
    const float* b_dr  = (const float*)d_in[3];
    const float* w_ih  = (const float*)d_in[4];
    const float* w_hh  = (const float*)d_in[5];
    const float* b_ih  = (const float*)d_in[6];
    const float* b_hh  = (const float*)d_in[7];
    const float* w_reg = (const float*)d_in[8];
    const float* b_reg = (const float*)d_in[9];
    const float* nlm_w1 = (const float*)d_in[10];
    const float* nlm_b1 = (const float*)d_in[11];
    const float* nlm_w2 = (const float*)d_in[12];
    const float* nlm_b2 = (const float*)d_in[13];
    const float* lm_w   = (const float*)d_in[14];
    const float* lm_b   = (const float*)d_in[15];
    float* out = (float*)d_out;

    float* qq;   cudaGetSymbolAddress((void**)&qq,   g_q);

    static bool attr_done = false;
    if (!attr_done) {
        cudaFuncSetAttribute(mega_kernel,
                             cudaFuncAttributeMaxDynamicSharedMemorySize, G1_DYN);
        attr_done = true;
    }

    // reset flags/counters (graph replays)
    init_kernel<<<1, 128>>>();
    // fused producer/consumer; GRU computes q inline (warp 7)
    mega_kernel<<<GRID_MEGA, 256, G1_DYN>>>(x, w_dr, b_dr, w_ih, b_ih,
                                            w_hh, b_hh, w_reg, b_reg);
    // sitp windows + heads
    sitp_kernel<<<B_, T_>>>(qq, x_len, nlm_w1, nlm_b1, nlm_w2, nlm_b2,
                            lm_w, lm_b, out);
}